// round 2
// baseline (speedup 1.0000x reference)
#include <cuda_runtime.h>
#include <cstdint>

// GCN_79568564126323: 2-layer GCN, N=200000, E=3200000, dims 4 -> 16 -> 1.
// Restructure: aggregate BEFORE the dense matmul on both layers:
//   layer1: agg1 = A_n x   (4 floats/node), h = relu(agg1@W1 + b1)
//   layer2: z = h@W2 (scalar/node), out = A_n z + b2
// => 1 red.v4.f32 per edge (layer1) + 1 scalar RED per edge (layer2).
//
// NOTE: edge_index is int32 (JAX x64 disabled -> int64 request silently
// becomes int32). Reading it as int64 was the R1 illegal-access bug.

#define N_MAX 200000

__device__ float  g_deg [N_MAX];
__device__ float  g_dinv[N_MAX];
__device__ float4 g_agg1[N_MAX];   // aggregated raw features (4 per node)
__device__ float  g_z   [N_MAX];   // relu(agg1 @ W1 + b1) @ W2

// ---------------------------------------------------------------- kernels

__global__ void k_init_deg(int n) {
    int i = blockIdx.x * blockDim.x + threadIdx.x;
    if (i < n) g_deg[i] = 1.0f;            // self-loop
}

__global__ void k_count_deg(const int* __restrict__ dst, int e) {
    int i = blockIdx.x * blockDim.x + threadIdx.x;
    if (i < e) atomicAdd(&g_deg[dst[i]], 1.0f);
}

// dinv = rsqrt(deg); agg1 init with the self-loop term x[v]*dinv^2
__global__ void k_dinv_and_selfloop(const float4* __restrict__ x, int n) {
    int i = blockIdx.x * blockDim.x + threadIdx.x;
    if (i >= n) return;
    float di = rsqrtf(g_deg[i]);           // deg >= 1 always (self loop)
    g_dinv[i] = di;
    float w = di * di;
    float4 xv = x[i];
    g_agg1[i] = make_float4(xv.x * w, xv.y * w, xv.z * w, xv.w * w);
}

// layer-1 edge scatter: agg1[dst] += x[src] * dinv[src]*dinv[dst]
__global__ void k_scatter1(const int*    __restrict__ src,
                           const int*    __restrict__ dst,
                           const float4* __restrict__ x, int e) {
    int i = blockIdx.x * blockDim.x + threadIdx.x;
    if (i >= e) return;
    int s = src[i];
    int d = dst[i];
    float w = g_dinv[s] * g_dinv[d];
    float4 xv = x[s];
    float a0 = xv.x * w, a1 = xv.y * w, a2 = xv.z * w, a3 = xv.w * w;
    unsigned long long gp =
        (unsigned long long)__cvta_generic_to_global(&g_agg1[d]);
    asm volatile("red.global.add.v4.f32 [%0], {%1, %2, %3, %4};"
                 :: "l"(gp), "f"(a0), "f"(a1), "f"(a2), "f"(a3)
                 : "memory");
}

// per-node dense: h = agg1 @ W1 + b1 ; z = relu(h) @ W2 ;
// out init = self-loop term z*dinv^2 + b2
__global__ void k_dense(const float* __restrict__ W1,
                        const float* __restrict__ b1,
                        const float* __restrict__ W2,
                        const float* __restrict__ b2,
                        float* __restrict__ out, int n) {
    int i = blockIdx.x * blockDim.x + threadIdx.x;
    if (i >= n) return;
    float4 a = g_agg1[i];
    float z = 0.0f;
#pragma unroll
    for (int j = 0; j < 16; j++) {
        float h = b1[j];
        h = fmaf(a.x, W1[ 0 + j], h);
        h = fmaf(a.y, W1[16 + j], h);
        h = fmaf(a.z, W1[32 + j], h);
        h = fmaf(a.w, W1[48 + j], h);
        h = fmaxf(h, 0.0f);
        z = fmaf(h, W2[j], z);
    }
    g_z[i] = z;
    float di = g_dinv[i];
    out[i] = fmaf(z, di * di, b2[0]);
}

// layer-2 edge scatter: out[dst] += z[src] * dinv[src]*dinv[dst]
__global__ void k_scatter2(const int* __restrict__ src,
                           const int* __restrict__ dst,
                           float* __restrict__ out, int e) {
    int i = blockIdx.x * blockDim.x + threadIdx.x;
    if (i >= e) return;
    int s = src[i];
    int d = dst[i];
    float v = g_z[s] * g_dinv[s] * g_dinv[d];
    atomicAdd(&out[d], v);   // compiles to RED (result unused)
}

// ---------------------------------------------------------------- launch

extern "C" void kernel_launch(void* const* d_in, const int* in_sizes, int n_in,
                              void* d_out, int out_size) {
    const float* x   = (const float*)d_in[0];   // [N,4] f32
    const int*   ei  = (const int*)d_in[1];     // [2,E] int32
    const float* W1  = (const float*)d_in[2];   // [4,16]
    const float* b1  = (const float*)d_in[3];   // [16]
    const float* W2  = (const float*)d_in[4];   // [16,1]
    const float* b2  = (const float*)d_in[5];   // [1]
    float*       out = (float*)d_out;           // [N,1]

    const int n = in_sizes[0] / 4;
    const int e = in_sizes[1] / 2;
    const int* src = ei;
    const int* dst = ei + e;

    const int T  = 256;
    const int gn = (n + T - 1) / T;
    const int ge = (e + T - 1) / T;

    k_init_deg         <<<gn, T>>>(n);
    k_count_deg        <<<ge, T>>>(dst, e);
    k_dinv_and_selfloop<<<gn, T>>>((const float4*)x, n);
    k_scatter1         <<<ge, T>>>(src, dst, (const float4*)x, e);
    k_dense            <<<gn, T>>>(W1, b1, W2, b2, out, n);
    k_scatter2         <<<ge, T>>>(src, dst, out, e);
}

// round 3
// speedup vs baseline: 1.4016x; 1.4016x over previous
#include <cuda_runtime.h>
#include <cstdint>

// GCN_79568564126323: 2-layer GCN, N=200000, E=3200000, dims 4 -> 16 -> 1.
//
// Aggregate-before-matmul + normalization factored OUT of the edge loops:
//   agg[d]  = dinv[d] * ( sum_{s->d} xs[s] + xs[d] ),  xs = x*dinv
//   h       = relu(agg @ W1 + b1), z = h @ W2, zs = z*dinv
//   out[d]  = dinv[d] * ( sum_{s->d} zs[s] + zs[d] ) + b2
// Edge loops do ONE gather + ONE RED each (no dinv gathers).

#define N_MAX 200000

__device__ float  g_deg [N_MAX];
__device__ float  g_dinv[N_MAX];
__device__ float4 g_xs  [N_MAX];   // x * dinv[src-side]
__device__ float4 g_agg [N_MAX];   // pre-dinv[d] aggregate
__device__ float  g_zs  [N_MAX];   // z * dinv[src-side]

// ---------------------------------------------------------------- kernels

__global__ void k_init_deg(int n) {
    int i = blockIdx.x * blockDim.x + threadIdx.x;
    if (i < n) g_deg[i] = 1.0f;            // self-loop
}

__global__ void k_count_deg(const int* __restrict__ dst, int e) {
    int i  = blockIdx.x * blockDim.x + threadIdx.x;
    int e4 = e >> 2;
    if (i < e4) {
        int4 d = ((const int4*)dst)[i];
        atomicAdd(&g_deg[d.x], 1.0f);
        atomicAdd(&g_deg[d.y], 1.0f);
        atomicAdd(&g_deg[d.z], 1.0f);
        atomicAdd(&g_deg[d.w], 1.0f);
    } else {
        int t = (e4 << 2) + (i - e4);      // tail edges
        if (t < e) atomicAdd(&g_deg[dst[t]], 1.0f);
    }
}

// dinv = rsqrt(deg); xs = x*dinv; agg init with self-loop term xs
__global__ void k_prep(const float4* __restrict__ x, int n) {
    int i = blockIdx.x * blockDim.x + threadIdx.x;
    if (i >= n) return;
    float di = rsqrtf(g_deg[i]);           // deg >= 1 (self loop)
    g_dinv[i] = di;
    float4 xv = x[i];
    float4 xs = make_float4(xv.x * di, xv.y * di, xv.z * di, xv.w * di);
    g_xs[i]  = xs;
    g_agg[i] = xs;                          // self-loop contribution
}

__device__ __forceinline__ void red_v4(float4* p, float4 v) {
    unsigned long long gp = (unsigned long long)__cvta_generic_to_global(p);
    asm volatile("red.global.add.v4.f32 [%0], {%1, %2, %3, %4};"
                 :: "l"(gp), "f"(v.x), "f"(v.y), "f"(v.z), "f"(v.w)
                 : "memory");
}

// layer-1 edge scatter: agg[d] += xs[s]   (4 edges per thread)
__global__ void k_scatter1(const int* __restrict__ src,
                           const int* __restrict__ dst, int e) {
    int i  = blockIdx.x * blockDim.x + threadIdx.x;
    int e4 = e >> 2;
    if (i < e4) {
        int4 s = ((const int4*)src)[i];
        int4 d = ((const int4*)dst)[i];
        float4 v0 = g_xs[s.x];
        float4 v1 = g_xs[s.y];
        float4 v2 = g_xs[s.z];
        float4 v3 = g_xs[s.w];
        red_v4(&g_agg[d.x], v0);
        red_v4(&g_agg[d.y], v1);
        red_v4(&g_agg[d.z], v2);
        red_v4(&g_agg[d.w], v3);
    } else {
        int t = (e4 << 2) + (i - e4);
        if (t < e) red_v4(&g_agg[dst[t]], g_xs[src[t]]);
    }
}

// per-node dense: a = agg*dinv; h = a@W1+b1; z = relu(h)@W2;
// zs = z*dinv; out init = self-loop term zs
__global__ void k_dense(const float* __restrict__ W1,
                        const float* __restrict__ b1,
                        const float* __restrict__ W2,
                        float* __restrict__ out, int n) {
    int i = blockIdx.x * blockDim.x + threadIdx.x;
    if (i >= n) return;
    float  di = g_dinv[i];
    float4 a  = g_agg[i];
    a.x *= di; a.y *= di; a.z *= di; a.w *= di;
    float z = 0.0f;
#pragma unroll
    for (int j = 0; j < 16; j++) {
        float h = b1[j];
        h = fmaf(a.x, W1[ 0 + j], h);
        h = fmaf(a.y, W1[16 + j], h);
        h = fmaf(a.z, W1[32 + j], h);
        h = fmaf(a.w, W1[48 + j], h);
        h = fmaxf(h, 0.0f);
        z = fmaf(h, W2[j], z);
    }
    float zs = z * di;
    g_zs[i] = zs;
    out[i]  = zs;                           // self-loop contribution
}

// layer-2 edge scatter: out[d] += zs[s]   (4 edges per thread)
__global__ void k_scatter2(const int* __restrict__ src,
                           const int* __restrict__ dst,
                           float* __restrict__ out, int e) {
    int i  = blockIdx.x * blockDim.x + threadIdx.x;
    int e4 = e >> 2;
    if (i < e4) {
        int4 s = ((const int4*)src)[i];
        int4 d = ((const int4*)dst)[i];
        float v0 = g_zs[s.x];
        float v1 = g_zs[s.y];
        float v2 = g_zs[s.z];
        float v3 = g_zs[s.w];
        atomicAdd(&out[d.x], v0);
        atomicAdd(&out[d.y], v1);
        atomicAdd(&out[d.z], v2);
        atomicAdd(&out[d.w], v3);
    } else {
        int t = (e4 << 2) + (i - e4);
        if (t < e) atomicAdd(&out[dst[t]], g_zs[src[t]]);
    }
}

// final per-node scale: out = out*dinv + b2
__global__ void k_final(const float* __restrict__ b2,
                        float* __restrict__ out, int n) {
    int i = blockIdx.x * blockDim.x + threadIdx.x;
    if (i < n) out[i] = fmaf(out[i], g_dinv[i], b2[0]);
}

// ---------------------------------------------------------------- launch

extern "C" void kernel_launch(void* const* d_in, const int* in_sizes, int n_in,
                              void* d_out, int out_size) {
    const float* x   = (const float*)d_in[0];   // [N,4] f32
    const int*   ei  = (const int*)d_in[1];     // [2,E] int32
    const float* W1  = (const float*)d_in[2];   // [4,16]
    const float* b1  = (const float*)d_in[3];   // [16]
    const float* W2  = (const float*)d_in[4];   // [16,1]
    const float* b2  = (const float*)d_in[5];   // [1]
    float*       out = (float*)d_out;           // [N,1]

    const int n = in_sizes[0] / 4;
    const int e = in_sizes[1] / 2;
    const int* src = ei;
    const int* dst = ei + e;

    const int T  = 256;
    const int gn = (n + T - 1) / T;
    // edge kernels: e/4 vector threads + (e%4) tail threads
    const int e4 = e >> 2;
    const int et = e4 + (e & 3);
    const int ge = (et + T - 1) / T;

    k_init_deg <<<gn, T>>>(n);
    k_count_deg<<<ge, T>>>(dst, e);
    k_prep     <<<gn, T>>>((const float4*)x, n);
    k_scatter1 <<<ge, T>>>(src, dst, e);
    k_dense    <<<gn, T>>>(W1, b1, W2, out, n);
    k_scatter2 <<<ge, T>>>(src, dst, out, e);
    k_final    <<<gn, T>>>(b2, out, n);
}